// round 5
// baseline (speedup 1.0000x reference)
#include <cuda_runtime.h>

#define NMAX 100000
#define CDIM 64
#define NSN 16

// ---- scratch (device globals; no allocation allowed) ----
__device__ float g_xq[NMAX * CDIM];
__device__ float g_kv[NMAX * 128];   // interleaved: [n][c*2] = k, [n][c*2+1] = v

// ---------------------------------------------------------------------------
// Kernel 1: y_{q,k,v} = x @ W^T + b.  Block = 64 rows x 64 cols, 256 threads,
// 4x4 register tile per thread. W transposed into smem during staging.
// q -> g_xq; k,v -> interleaved g_kv.
// ---------------------------------------------------------------------------
__global__ __launch_bounds__(256) void proj3_kernel(
    const float* __restrict__ x,
    const float* __restrict__ Wq, const float* __restrict__ bq,
    const float* __restrict__ Wk, const float* __restrict__ bk,
    const float* __restrict__ Wv, const float* __restrict__ bv, int n)
{
    __shared__ __align__(16) float xsT[64][68];   // xsT[k][r]
    __shared__ __align__(16) float WT[64][68];    // WT[k][c]
    __shared__ float bias[64];

    int t = threadIdx.x;
    int row0 = blockIdx.x * 64;

    // load x tile transposed (coalesced global read)
    for (int i = t; i < 64 * 64; i += 256) {
        int r = i >> 6, k = i & 63;
        int rr = row0 + r;
        xsT[k][r] = (rr < n) ? x[rr * 64 + k] : 0.f;
    }

    int tx = t & 15;   // col group (4 cols)
    int ty = t >> 4;   // row group (4 rows)

    const float* Ws[3] = { Wq, Wk, Wv };
    const float* bs[3] = { bq, bk, bv };

#pragma unroll
    for (int m = 0; m < 3; m++) {
        __syncthreads();
        // stage W transposed: read W[c*64+k] coalesced, write WT[k][c]
        for (int i = t; i < 64 * 64; i += 256) {
            int c = i >> 6, k = i & 63;
            WT[k][c] = Ws[m][i];
        }
        if (t < 64) bias[t] = bs[m][t];
        __syncthreads();

        float acc[4][4];
#pragma unroll
        for (int i = 0; i < 4; i++)
#pragma unroll
            for (int j = 0; j < 4; j++) acc[i][j] = 0.f;

#pragma unroll 8
        for (int k = 0; k < 64; k++) {
            float4 a4 = *(const float4*)&xsT[k][ty * 4];
            float4 b4 = *(const float4*)&WT[k][tx * 4];
            float a[4] = { a4.x, a4.y, a4.z, a4.w };
            float b[4] = { b4.x, b4.y, b4.z, b4.w };
#pragma unroll
            for (int i = 0; i < 4; i++)
#pragma unroll
                for (int j = 0; j < 4; j++)
                    acc[i][j] = fmaf(a[i], b[j], acc[i][j]);
        }

#pragma unroll
        for (int i = 0; i < 4; i++) {
            int r = row0 + ty * 4 + i;
            if (r < n) {
#pragma unroll
                for (int j = 0; j < 4; j++) {
                    int cc = tx * 4 + j;
                    float val = acc[i][j] + bias[cc];
                    if (m == 0)      g_xq[r * 64 + cc] = val;
                    else             g_kv[r * 128 + cc * 2 + (m - 1)] = val;
                }
            }
        }
    }
}

// ---------------------------------------------------------------------------
// Kernel 2: fused per-point attention. 4 points/block, 64 threads/point
// (thread = channel). Vectorized/broadcast smem access throughout.
// ---------------------------------------------------------------------------
__global__ __launch_bounds__(256, 3) void attn_kernel(
    const float* __restrict__ p, const int* __restrict__ idx,
    const float* __restrict__ pw1, const float* __restrict__ pb1,
    const float* __restrict__ pbng, const float* __restrict__ pbnb,
    const float* __restrict__ pbnm, const float* __restrict__ pbnv,
    const float* __restrict__ pw2, const float* __restrict__ pb2,
    const float* __restrict__ bn1g, const float* __restrict__ bn1b,
    const float* __restrict__ bn1m, const float* __restrict__ bn1v,
    const float* __restrict__ ww1, const float* __restrict__ wb1,
    const float* __restrict__ bn2g, const float* __restrict__ bn2b,
    const float* __restrict__ bn2m, const float* __restrict__ bn2v,
    const float* __restrict__ ww2, const float* __restrict__ wb2,
    float* __restrict__ out, int n)
{
    __shared__ __align__(16) float s_wbuf[4][16][68];  // relu(bn1(w))
    __shared__ __align__(16) float s_u[4][16][8];
    __shared__ float s_lg[4][16][8];
    __shared__ __align__(16) int   s_j[4][16];
    __shared__ __align__(16) float4 s_pr4[4][16];      // post-ReLU p_r (x,y,z,-)
    __shared__ __align__(16) float s_w1J[8][64];       // ww1 rows (j-major)
    __shared__ float s_pw2[64][3];
    __shared__ float s_sc1[64], s_sh1[64], s_pb2[64];
    __shared__ __align__(16) float s_w2T[8][8];        // w_w2 transposed
    __shared__ float s_b1[8], s_sc2[8], s_sh2[8], s_b2[8];
    __shared__ float s_pw1[9], s_pb1[3], s_psc[3], s_psh[3];

    int t = threadIdx.x;

    // ---- fold BN params + stage weights in smem ----
    if (t < 64) {
        float sc = bn1g[t] * rsqrtf(bn1v[t] + 1e-5f);
        s_sc1[t] = sc;
        s_sh1[t] = bn1b[t] - bn1m[t] * sc;
        s_pb2[t] = pb2[t];
#pragma unroll
        for (int j = 0; j < 8; j++) s_w1J[j][t] = ww1[j * 64 + t];
        s_pw2[t][0] = pw2[t * 3 + 0];
        s_pw2[t][1] = pw2[t * 3 + 1];
        s_pw2[t][2] = pw2[t * 3 + 2];
    } else if (t < 72) {
        int q = t - 64;
        float sc = bn2g[q] * rsqrtf(bn2v[q] + 1e-5f);
        s_sc2[q] = sc;
        s_sh2[q] = bn2b[q] - bn2m[q] * sc;
        s_b1[q] = wb1[q];
        s_b2[q] = wb2[q];
    } else if (t >= 128 && t < 192) {
        int q = t - 128;                      // 64 threads -> all 64 entries
        int k = q >> 3, j = q & 7;
        s_w2T[k][j] = ww2[j * 8 + k];
    } else if (t >= 192 && t < 207) {
        int q = t - 192;
        if (q < 9) s_pw1[q] = pw1[q];
        else if (q < 12) s_pb1[q - 9] = pb1[q - 9];
        else {
            int k = q - 12;
            float sc = pbng[k] * rsqrtf(pbnv[k] + 1e-5f);
            s_psc[k] = sc;
            s_psh[k] = pbnb[k] - pbnm[k] * sc;
        }
    }
    __syncthreads();

    int pt = t >> 6;          // point slot within block (0..3)
    int c  = t & 63;          // channel
    int pid = blockIdx.x * 4 + pt;
    bool valid = pid < n;
    int n0 = valid ? pid : 0;

    // ---- Phase A0: 16 threads/point: load idx row + compute p_r 3-vec ----
    if (c < 16) {
        int j = idx[n0 * 16 + c];
        s_j[pt][c] = j;
        float px = p[n0 * 3 + 0], py = p[n0 * 3 + 1], pz = p[n0 * 3 + 2];
        float dx = p[j * 3 + 0] - px;
        float dy = p[j * 3 + 1] - py;
        float dz = p[j * 3 + 2] - pz;
        float r0 = fmaf(s_pw1[0], dx, fmaf(s_pw1[1], dy, fmaf(s_pw1[2], dz, s_pb1[0])));
        float r1 = fmaf(s_pw1[3], dx, fmaf(s_pw1[4], dy, fmaf(s_pw1[5], dz, s_pb1[1])));
        float r2 = fmaf(s_pw1[6], dx, fmaf(s_pw1[7], dy, fmaf(s_pw1[8], dz, s_pb1[2])));
        float4 rr;
        rr.x = fmaxf(fmaf(r0, s_psc[0], s_psh[0]), 0.f);
        rr.y = fmaxf(fmaf(r1, s_psc[1], s_psh[1]), 0.f);
        rr.z = fmaxf(fmaf(r2, s_psc[2], s_psh[2]), 0.f);
        rr.w = 0.f;
        s_pr4[pt][c] = rr;
    }
    __syncthreads();

    // ---- Phase A1: full-MLP gather of interleaved (k,v), 16 LDG.64 in flight ----
    int js[16];
    {
        const int4* jp = (const int4*)s_j[pt];
#pragma unroll
        for (int q = 0; q < 4; q++) {
            int4 v = jp[q];
            js[q * 4 + 0] = v.x; js[q * 4 + 1] = v.y;
            js[q * 4 + 2] = v.z; js[q * 4 + 3] = v.w;
        }
    }
    float2 kv[16];
    {
        int c2 = c * 2;
#pragma unroll
        for (int nb = 0; nb < 16; nb++)
            kv[nb] = *(const float2*)&g_kv[js[nb] * 128 + c2];
    }

    float xqc = g_xq[n0 * 64 + c];
    float sc1 = s_sc1[c], sh1 = s_sh1[c];
    float w2a = s_pw2[c][0], w2b = s_pw2[c][1], w2c = s_pw2[c][2];
    float pb2c = s_pb2[c];

    float vpr[16];
#pragma unroll
    for (int nb = 0; nb < 16; nb++) {
        float4 rr = s_pr4[pt][nb];
        float pr = fmaf(w2a, rr.x, fmaf(w2b, rr.y, fmaf(w2c, rr.z, pb2c)));
        float w = kv[nb].x - xqc + pr;
        s_wbuf[pt][nb][c] = fmaxf(fmaf(w, sc1, sh1), 0.f);
        vpr[nb] = kv[nb].y + pr;
    }
    __syncthreads();

    // ---- Phase B1: u = relu(bn2(wbuf @ w_w1^T + b1)). thread -> (nb, 2 j's) ----
    {
        int nb = c >> 2;
        int j0 = (c & 3) * 2;
        const float4* wrow = (const float4*)s_wbuf[pt][nb];
        const float4* w1a = (const float4*)s_w1J[j0];
        const float4* w1b = (const float4*)s_w1J[j0 + 1];
        float a0 = s_b1[j0], a1 = s_b1[j0 + 1];
#pragma unroll
        for (int k4 = 0; k4 < 16; k4++) {
            float4 wv = wrow[k4];
            float4 qa = w1a[k4];
            float4 qb = w1b[k4];
            a0 = fmaf(wv.x, qa.x, a0); a1 = fmaf(wv.x, qb.x, a1);
            a0 = fmaf(wv.y, qa.y, a0); a1 = fmaf(wv.y, qb.y, a1);
            a0 = fmaf(wv.z, qa.z, a0); a1 = fmaf(wv.z, qb.z, a1);
            a0 = fmaf(wv.w, qa.w, a0); a1 = fmaf(wv.w, qb.w, a1);
        }
        s_u[pt][nb][j0]     = fmaxf(fmaf(a0, s_sc2[j0],     s_sh2[j0]),     0.f);
        s_u[pt][nb][j0 + 1] = fmaxf(fmaf(a1, s_sc2[j0 + 1], s_sh2[j0 + 1]), 0.f);
    }
    __syncthreads();

    // ---- Phase B2: logits = u @ w_w2^T + b2 ----
    {
        int nb = c >> 2;
        int j0 = (c & 3) * 2;
        const float4* up = (const float4*)s_u[pt][nb];
        float4 u0 = up[0], u1 = up[1];
        float uu[8] = { u0.x, u0.y, u0.z, u0.w, u1.x, u1.y, u1.z, u1.w };
        float a0 = s_b2[j0], a1 = s_b2[j0 + 1];
#pragma unroll
        for (int k = 0; k < 8; k++) {
            float2 q = *(const float2*)&s_w2T[k][j0];
            a0 = fmaf(uu[k], q.x, a0);
            a1 = fmaf(uu[k], q.y, a1);
        }
        s_lg[pt][nb][j0] = a0;
        s_lg[pt][nb][j0 + 1] = a1;
    }
    __syncthreads();

    // ---- Phase C: softmax over neighbors (8 lanes per point active) ----
    if (c < 8) {
        int j = c;
        float m = -1e30f;
#pragma unroll
        for (int nb = 0; nb < 16; nb++) m = fmaxf(m, s_lg[pt][nb][j]);
        float e[16];
        float sum = 0.f;
#pragma unroll
        for (int nb = 0; nb < 16; nb++) {
            e[nb] = __expf(s_lg[pt][nb][j] - m);
            sum += e[nb];
        }
        float inv = 1.f / sum;
#pragma unroll
        for (int nb = 0; nb < 16; nb++) s_lg[pt][nb][j] = e[nb] * inv;
    }
    __syncthreads();

    // ---- Phase D: out[c] = sum_nb vpr[nb] * w[nb][c%8] ----
    if (valid) {
        int j = c & 7;
        float acc = 0.f;
#pragma unroll
        for (int nb = 0; nb < 16; nb++)
            acc = fmaf(vpr[nb], s_lg[pt][nb][j], acc);
        out[pid * 64 + c] = acc;
    }
}

// ---------------------------------------------------------------------------
extern "C" void kernel_launch(void* const* d_in, const int* in_sizes, int n_in,
                              void* d_out, int out_size)
{
    const float* p    = (const float*)d_in[0];
    const float* x    = (const float*)d_in[1];
    const int*   idx  = (const int*)d_in[2];
    const float* Wq   = (const float*)d_in[3];
    const float* bq   = (const float*)d_in[4];
    const float* Wk   = (const float*)d_in[5];
    const float* bk   = (const float*)d_in[6];
    const float* Wv   = (const float*)d_in[7];
    const float* bv   = (const float*)d_in[8];
    const float* pw1  = (const float*)d_in[9];
    const float* pb1  = (const float*)d_in[10];
    const float* pbng = (const float*)d_in[11];
    const float* pbnb = (const float*)d_in[12];
    const float* pbnm = (const float*)d_in[13];
    const float* pbnv = (const float*)d_in[14];
    const float* pw2  = (const float*)d_in[15];
    const float* pb2  = (const float*)d_in[16];
    const float* bn1g = (const float*)d_in[17];
    const float* bn1b = (const float*)d_in[18];
    const float* bn1m = (const float*)d_in[19];
    const float* bn1v = (const float*)d_in[20];
    const float* ww1  = (const float*)d_in[21];
    const float* wb1  = (const float*)d_in[22];
    const float* bn2g = (const float*)d_in[23];
    const float* bn2b = (const float*)d_in[24];
    const float* bn2m = (const float*)d_in[25];
    const float* bn2v = (const float*)d_in[26];
    const float* ww2  = (const float*)d_in[27];
    const float* wb2  = (const float*)d_in[28];

    int n = in_sizes[0] / 3;
    float* out = (float*)d_out;

    proj3_kernel<<<(n + 63) / 64, 256>>>(x, Wq, bq, Wk, bk, Wv, bv, n);
    attn_kernel<<<(n + 3) / 4, 256>>>(
        p, idx, pw1, pb1, pbng, pbnb, pbnm, pbnv, pw2, pb2,
        bn1g, bn1b, bn1m, bn1v, ww1, wb1,
        bn2g, bn2b, bn2m, bn2v, ww2, wb2,
        out, n);
}

// round 6
// speedup vs baseline: 1.7808x; 1.7808x over previous
#include <cuda_runtime.h>

#define NMAX 100000
#define CDIM 64
#define NSN 16

// ---- scratch (device globals; no allocation allowed) ----
__device__ float g_xq[NMAX * CDIM];
__device__ float g_kv[NMAX * 128];   // interleaved: [n][c*2] = k, [n][c*2+1] = v

// ---------------------------------------------------------------------------
// Kernel 1: y_{q,k,v} = x @ W^T + b.  Block = 64 rows x 64 cols, 256 threads,
// 4x4 register tile per thread. W transposed into smem during staging.
// ---------------------------------------------------------------------------
__global__ __launch_bounds__(256) void proj3_kernel(
    const float* __restrict__ x,
    const float* __restrict__ Wq, const float* __restrict__ bq,
    const float* __restrict__ Wk, const float* __restrict__ bk,
    const float* __restrict__ Wv, const float* __restrict__ bv, int n)
{
    __shared__ __align__(16) float xsT[64][68];   // xsT[k][r]
    __shared__ __align__(16) float WT[64][68];    // WT[k][c]
    __shared__ float bias[64];

    int t = threadIdx.x;
    int row0 = blockIdx.x * 64;

    for (int i = t; i < 64 * 64; i += 256) {
        int r = i >> 6, k = i & 63;
        int rr = row0 + r;
        xsT[k][r] = (rr < n) ? x[rr * 64 + k] : 0.f;
    }

    int tx = t & 15;
    int ty = t >> 4;

    const float* Ws[3] = { Wq, Wk, Wv };
    const float* bs[3] = { bq, bk, bv };

#pragma unroll
    for (int m = 0; m < 3; m++) {
        __syncthreads();
        for (int i = t; i < 64 * 64; i += 256) {
            int c = i >> 6, k = i & 63;
            WT[k][c] = Ws[m][i];
        }
        if (t < 64) bias[t] = bs[m][t];
        __syncthreads();

        float acc[4][4];
#pragma unroll
        for (int i = 0; i < 4; i++)
#pragma unroll
            for (int j = 0; j < 4; j++) acc[i][j] = 0.f;

#pragma unroll 8
        for (int k = 0; k < 64; k++) {
            float4 a4 = *(const float4*)&xsT[k][ty * 4];
            float4 b4 = *(const float4*)&WT[k][tx * 4];
            float a[4] = { a4.x, a4.y, a4.z, a4.w };
            float b[4] = { b4.x, b4.y, b4.z, b4.w };
#pragma unroll
            for (int i = 0; i < 4; i++)
#pragma unroll
                for (int j = 0; j < 4; j++)
                    acc[i][j] = fmaf(a[i], b[j], acc[i][j]);
        }

#pragma unroll
        for (int i = 0; i < 4; i++) {
            int r = row0 + ty * 4 + i;
            if (r < n) {
#pragma unroll
                for (int j = 0; j < 4; j++) {
                    int cc = tx * 4 + j;
                    float val = acc[i][j] + bias[cc];
                    if (m == 0)      g_xq[r * 64 + cc] = val;
                    else             g_kv[r * 128 + cc * 2 + (m - 1)] = val;
                }
            }
        }
    }
}

// ---------------------------------------------------------------------------
// Kernel 2: fused per-point attention. 4 points/block, 64 threads/point.
// Bank-conflict-free padded smem layouts; gather in two 8-neighbor halves
// to fit 64 regs -> 4 blocks/SM.
// ---------------------------------------------------------------------------
__global__ __launch_bounds__(256, 4) void attn_kernel(
    const float* __restrict__ p, const int* __restrict__ idx,
    const float* __restrict__ pw1, const float* __restrict__ pb1,
    const float* __restrict__ pbng, const float* __restrict__ pbnb,
    const float* __restrict__ pbnm, const float* __restrict__ pbnv,
    const float* __restrict__ pw2, const float* __restrict__ pb2,
    const float* __restrict__ bn1g, const float* __restrict__ bn1b,
    const float* __restrict__ bn1m, const float* __restrict__ bn1v,
    const float* __restrict__ ww1, const float* __restrict__ wb1,
    const float* __restrict__ bn2g, const float* __restrict__ bn2b,
    const float* __restrict__ bn2m, const float* __restrict__ bn2v,
    const float* __restrict__ ww2, const float* __restrict__ wb2,
    float* __restrict__ out, int n)
{
    __shared__ __align__(16) float s_wbuf[4][16][68];  // relu(bn1(w)); stride 68 cf-free
    __shared__ __align__(16) float s_u[4][16][12];     // stride 12: float4 cf-free
    __shared__ float s_lg[4][16][9];                   // stride 9: col reads cf-free
    __shared__ __align__(16) int   s_j[4][16];
    __shared__ __align__(16) float4 s_pr4[4][16];      // post-ReLU p_r (x,y,z,-)
    __shared__ __align__(16) float s_w1J[8][68];       // ww1 rows, padded 68
    __shared__ float s_pw2[64][3];
    __shared__ float s_sc1[64], s_sh1[64], s_pb2[64];
    __shared__ __align__(16) float s_w2T[8][8];        // w_w2 transposed
    __shared__ float s_b1[8], s_sc2[8], s_sh2[8], s_b2[8];
    __shared__ float s_pw1[9], s_pb1[3], s_psc[3], s_psh[3];

    int t = threadIdx.x;

    // ---- fold BN params + stage weights in smem ----
    if (t < 64) {
        float sc = bn1g[t] * rsqrtf(bn1v[t] + 1e-5f);
        s_sc1[t] = sc;
        s_sh1[t] = bn1b[t] - bn1m[t] * sc;
        s_pb2[t] = pb2[t];
#pragma unroll
        for (int j = 0; j < 8; j++) s_w1J[j][t] = ww1[j * 64 + t];
        s_pw2[t][0] = pw2[t * 3 + 0];
        s_pw2[t][1] = pw2[t * 3 + 1];
        s_pw2[t][2] = pw2[t * 3 + 2];
    } else if (t < 72) {
        int q = t - 64;
        float sc = bn2g[q] * rsqrtf(bn2v[q] + 1e-5f);
        s_sc2[q] = sc;
        s_sh2[q] = bn2b[q] - bn2m[q] * sc;
        s_b1[q] = wb1[q];
        s_b2[q] = wb2[q];
    } else if (t >= 128 && t < 192) {
        int q = t - 128;
        int k = q >> 3, j = q & 7;
        s_w2T[k][j] = ww2[j * 8 + k];
    } else if (t >= 192 && t < 207) {
        int q = t - 192;
        if (q < 9) s_pw1[q] = pw1[q];
        else if (q < 12) s_pb1[q - 9] = pb1[q - 9];
        else {
            int k = q - 12;
            float sc = pbng[k] * rsqrtf(pbnv[k] + 1e-5f);
            s_psc[k] = sc;
            s_psh[k] = pbnb[k] - pbnm[k] * sc;
        }
    }
    __syncthreads();

    int pt = t >> 6;          // point slot within block (0..3)
    int c  = t & 63;          // channel
    int pid = blockIdx.x * 4 + pt;
    bool valid = pid < n;
    int n0 = valid ? pid : 0;

    // ---- Phase A0: 16 threads/point: load idx row + compute p_r 3-vec ----
    if (c < 16) {
        int j = idx[n0 * 16 + c];
        s_j[pt][c] = j;
        float px = p[n0 * 3 + 0], py = p[n0 * 3 + 1], pz = p[n0 * 3 + 2];
        float dx = p[j * 3 + 0] - px;
        float dy = p[j * 3 + 1] - py;
        float dz = p[j * 3 + 2] - pz;
        float r0 = fmaf(s_pw1[0], dx, fmaf(s_pw1[1], dy, fmaf(s_pw1[2], dz, s_pb1[0])));
        float r1 = fmaf(s_pw1[3], dx, fmaf(s_pw1[4], dy, fmaf(s_pw1[5], dz, s_pb1[1])));
        float r2 = fmaf(s_pw1[6], dx, fmaf(s_pw1[7], dy, fmaf(s_pw1[8], dz, s_pb1[2])));
        float4 rr;
        rr.x = fmaxf(fmaf(r0, s_psc[0], s_psh[0]), 0.f);
        rr.y = fmaxf(fmaf(r1, s_psc[1], s_psh[1]), 0.f);
        rr.z = fmaxf(fmaf(r2, s_psc[2], s_psh[2]), 0.f);
        rr.w = 0.f;
        s_pr4[pt][c] = rr;
    }
    __syncthreads();

    float xqc = g_xq[n0 * 64 + c];
    float sc1 = s_sc1[c], sh1 = s_sh1[c];
    float w2a = s_pw2[c][0], w2b = s_pw2[c][1], w2c = s_pw2[c][2];
    float pb2c = s_pb2[c];

    // ---- Phase A1: gather (k,v) in two 8-neighbor halves (8 LDG.64 in flight) ----
    float vpr[16];
    int c2 = c * 2;
#pragma unroll
    for (int h = 0; h < 2; h++) {
        int js[8];
        {
            const int4* jp = (const int4*)&s_j[pt][h * 8];
            int4 v0 = jp[0], v1 = jp[1];
            js[0] = v0.x; js[1] = v0.y; js[2] = v0.z; js[3] = v0.w;
            js[4] = v1.x; js[5] = v1.y; js[6] = v1.z; js[7] = v1.w;
        }
        float2 kv[8];
#pragma unroll
        for (int q = 0; q < 8; q++)
            kv[q] = *(const float2*)&g_kv[js[q] * 128 + c2];
#pragma unroll
        for (int q = 0; q < 8; q++) {
            int nb = h * 8 + q;
            float4 rr = s_pr4[pt][nb];
            float pr = fmaf(w2a, rr.x, fmaf(w2b, rr.y, fmaf(w2c, rr.z, pb2c)));
            float w = kv[q].x - xqc + pr;
            s_wbuf[pt][nb][c] = fmaxf(fmaf(w, sc1, sh1), 0.f);
            vpr[nb] = kv[q].y + pr;
        }
    }
    __syncthreads();

    // ---- Phase B1: u = relu(bn2(wbuf @ w_w1^T + b1)). thread -> (nb, 2 j's) ----
    {
        int nb = c >> 2;
        int j0 = (c & 3) * 2;
        const float4* wrow = (const float4*)s_wbuf[pt][nb];
        const float4* w1a = (const float4*)s_w1J[j0];
        const float4* w1b = (const float4*)s_w1J[j0 + 1];
        float a0 = s_b1[j0], a1 = s_b1[j0 + 1];
#pragma unroll
        for (int k4 = 0; k4 < 16; k4++) {
            float4 wv = wrow[k4];
            float4 qa = w1a[k4];
            float4 qb = w1b[k4];
            a0 = fmaf(wv.x, qa.x, a0); a1 = fmaf(wv.x, qb.x, a1);
            a0 = fmaf(wv.y, qa.y, a0); a1 = fmaf(wv.y, qb.y, a1);
            a0 = fmaf(wv.z, qa.z, a0); a1 = fmaf(wv.z, qb.z, a1);
            a0 = fmaf(wv.w, qa.w, a0); a1 = fmaf(wv.w, qb.w, a1);
        }
        s_u[pt][nb][j0]     = fmaxf(fmaf(a0, s_sc2[j0],     s_sh2[j0]),     0.f);
        s_u[pt][nb][j0 + 1] = fmaxf(fmaf(a1, s_sc2[j0 + 1], s_sh2[j0 + 1]), 0.f);
    }
    __syncthreads();

    // ---- Phase B2: logits = u @ w_w2^T + b2 ----
    {
        int nb = c >> 2;
        int j0 = (c & 3) * 2;
        const float4* up = (const float4*)s_u[pt][nb];
        float4 u0 = up[0], u1 = up[1];
        float uu[8] = { u0.x, u0.y, u0.z, u0.w, u1.x, u1.y, u1.z, u1.w };
        float a0 = s_b2[j0], a1 = s_b2[j0 + 1];
#pragma unroll
        for (int k = 0; k < 8; k++) {
            float2 q = *(const float2*)&s_w2T[k][j0];
            a0 = fmaf(uu[k], q.x, a0);
            a1 = fmaf(uu[k], q.y, a1);
        }
        s_lg[pt][nb][j0] = a0;
        s_lg[pt][nb][j0 + 1] = a1;
    }
    __syncthreads();

    // ---- Phase C: softmax over neighbors (8 lanes per point active) ----
    if (c < 8) {
        int j = c;
        float m = -1e30f;
#pragma unroll
        for (int nb = 0; nb < 16; nb++) m = fmaxf(m, s_lg[pt][nb][j]);
        float e[16];
        float sum = 0.f;
#pragma unroll
        for (int nb = 0; nb < 16; nb++) {
            e[nb] = __expf(s_lg[pt][nb][j] - m);
            sum += e[nb];
        }
        float inv = 1.f / sum;
#pragma unroll
        for (int nb = 0; nb < 16; nb++) s_lg[pt][nb][j] = e[nb] * inv;
    }
    __syncthreads();

    // ---- Phase D: out[c] = sum_nb vpr[nb] * w[nb][c%8] ----
    if (valid) {
        int j = c & 7;
        float acc = 0.f;
#pragma unroll
        for (int nb = 0; nb < 16; nb++)
            acc = fmaf(vpr[nb], s_lg[pt][nb][j], acc);
        out[pid * 64 + c] = acc;
    }
}

// ---------------------------------------------------------------------------
extern "C" void kernel_launch(void* const* d_in, const int* in_sizes, int n_in,
                              void* d_out, int out_size)
{
    const float* p    = (const float*)d_in[0];
    const float* x    = (const float*)d_in[1];
    const int*   idx  = (const int*)d_in[2];
    const float* Wq   = (const float*)d_in[3];
    const float* bq   = (const float*)d_in[4];
    const float* Wk   = (const float*)d_in[5];
    const float* bk   = (const float*)d_in[6];
    const float* Wv   = (const float*)d_in[7];
    const float* bv   = (const float*)d_in[8];
    const float* pw1  = (const float*)d_in[9];
    const float* pb1  = (const float*)d_in[10];
    const float* pbng = (const float*)d_in[11];
    const float* pbnb = (const float*)d_in[12];
    const float* pbnm = (const float*)d_in[13];
    const float* pbnv = (const float*)d_in[14];
    const float* pw2  = (const float*)d_in[15];
    const float* pb2  = (const float*)d_in[16];
    const float* bn1g = (const float*)d_in[17];
    const float* bn1b = (const float*)d_in[18];
    const float* bn1m = (const float*)d_in[19];
    const float* bn1v = (const float*)d_in[20];
    const float* ww1  = (const float*)d_in[21];
    const float* wb1  = (const float*)d_in[22];
    const float* bn2g = (const float*)d_in[23];
    const float* bn2b = (const float*)d_in[24];
    const float* bn2m = (const float*)d_in[25];
    const float* bn2v = (const float*)d_in[26];
    const float* ww2  = (const float*)d_in[27];
    const float* wb2  = (const float*)d_in[28];

    int n = in_sizes[0] / 3;
    float* out = (float*)d_out;

    proj3_kernel<<<(n + 63) / 64, 256>>>(x, Wq, bq, Wk, bk, Wv, bv, n);
    attn_kernel<<<(n + 3) / 4, 256>>>(
        p, idx, pw1, pb1, pbng, pbnb, pbnm, pbnv, pw2, pb2,
        bn1g, bn1b, bn1m, bn1v, ww1, wb1,
        bn2g, bn2b, bn2m, bn2v, ww2, wb2,
        out, n);
}